// round 15
// baseline (speedup 1.0000x reference)
#include <cuda_runtime.h>
#include <cuda_fp16.h>
#include <math.h>
#include <stdint.h>

// ---------------- problem constants (fixed by setup_inputs) ----------------
#define BB   8
#define LQ   3072
#define CC   768
#define LIN  4096          // 64*64 feature tokens
#define HL   64
#define WL   64
#define NH   6
#define NP   4
#define HID  192
#define HH   32
#define WW   32
#define MQ   (BB*LQ)       // 24576
#define MF   (BB*LIN)      // 32768
#define NOA  72            // 48 offs + 24 attn logits, fused

// ---------------- scratch (device globals; no allocs allowed) --------------
__device__ __half g_qln16 [MQ*CC];
__device__ __half g_fln16 [MF*CC];
__device__ __half g_val16 [MF*CC];
__device__ __half g_attn16[MQ*CC];
__device__ __half g_x1h   [MQ*HID];
__device__ __half g_x2h   [MQ*HID];
__device__ __half g_q2h   [MQ*CC];
__device__ float  g_oa    [MQ*NOA];
// transposed fp16 weights [N][K]
__device__ __half g_vpT16 [CC*CC];
__device__ __half g_opT16 [CC*CC];
__device__ __half g_fc1T16[HID*CC];
__device__ __half g_fc2T16[CC*HID];
__device__ __half g_w72T16[NOA*CC];
__device__ float  g_b72   [NOA];

// ---------------- mma / ldmatrix / cp.async helpers -------------------------
__device__ __forceinline__ void mma_fp16(float* d, const uint32_t* a, const uint32_t* b) {
    asm volatile(
        "mma.sync.aligned.m16n8k16.row.col.f32.f16.f16.f32 "
        "{%0,%1,%2,%3}, {%4,%5,%6,%7}, {%8,%9}, {%0,%1,%2,%3};\n"
        : "+f"(d[0]), "+f"(d[1]), "+f"(d[2]), "+f"(d[3])
        : "r"(a[0]), "r"(a[1]), "r"(a[2]), "r"(a[3]), "r"(b[0]), "r"(b[1]));
}
__device__ __forceinline__ void ldsm_x4(uint32_t* r, uint32_t addr) {
    asm volatile("ldmatrix.sync.aligned.m8n8.x4.shared.b16 {%0,%1,%2,%3}, [%4];"
                 : "=r"(r[0]), "=r"(r[1]), "=r"(r[2]), "=r"(r[3]) : "r"(addr));
}
__device__ __forceinline__ void cp16(uint32_t dst, const void* src, bool valid) {
    int sz = valid ? 16 : 0;
    asm volatile("cp.async.cg.shared.global [%0], [%1], 16, %2;\n"
                 :: "r"(dst), "l"(src), "r"(sz));
}
__device__ __forceinline__ void cp_commit() { asm volatile("cp.async.commit_group;\n"); }
template <int N> __device__ __forceinline__ void cp_wait() {
    asm volatile("cp.async.wait_group %0;\n" :: "n"(N));
}

// ---------------- fp16 tensor-core GEMM body --------------------------------
#define ST 36                 // row stride in u32 (32 data + 4 pad) -> conflict-free
#define STB (ST*4)            // 144 bytes
#define TSZ (128 * ST)        // one tile (A or B) in u32 = 4608
#define SSZ (2 * TSZ)         // stage = A + B = 9216 u32
#define NSTAGE 3
#define GEMM_SMEM (NSTAGE * SSZ * 4)   // 110,592 B

__device__ __forceinline__ void gemm_body(
        const __half* __restrict__ A, const __half* __restrict__ WT,
        const float* __restrict__ bias, const float* __restrict__ R,
        const __half* __restrict__ Rh,
        float* __restrict__ C, __half* __restrict__ Ch,
        int M, int N, int K, int bx, int by) {
    extern __shared__ uint32_t sm[];

    const int t    = threadIdx.x;
    const int lane = t & 31;
    const int g    = lane >> 2;
    const int tg   = lane & 3;
    const int wid  = t >> 5;
    const int wm   = wid & 1;
    const int wn   = wid >> 1;

    const int m0 = by * 128;
    const int n0 = bx * 128;

    const int sr = t >> 3;
    const int sc = (t & 7) * 8;
    const uint32_t smem_u = (uint32_t)__cvta_generic_to_shared(sm);
    const uint32_t soff = (uint32_t)(sr * STB + (t & 7) * 16);

    const __half* Abase = A + (size_t)(m0 + sr) * K + sc;
    const __half* WTbase = WT + (size_t)sr * K + sc;

    const int KT = K >> 6;

    auto issue = [&](int ck, int s) {
        const uint32_t sb = smem_u + (uint32_t)(s * SSZ * 4);
        const __half* Ap = Abase + ck * 64;
        const __half* Bp = WTbase + ck * 64;
        #pragma unroll
        for (int j = 0; j < 4; ++j) {
            cp16(sb + soff + (uint32_t)(32 * j * STB),
                 Ap + (size_t)(32 * j) * K, true);
            const int nr = n0 + sr + 32 * j;
            cp16(sb + (uint32_t)(TSZ * 4) + soff + (uint32_t)(32 * j * STB),
                 Bp + (size_t)(n0 + 32 * j) * K, nr < N);
        }
    };

    const int rowA  = (lane & 7) + ((lane >> 3) & 1) * 8;
    const uint32_t kselA = (uint32_t)(lane >> 4) * 16;
    uint32_t aoff[4];
    #pragma unroll
    for (int mt = 0; mt < 4; ++mt)
        aoff[mt] = (uint32_t)((wm * 64 + mt * 16 + rowA) * STB) + kselA;
    const int rowB  = (lane & 7) + ((lane >> 4) & 1) * 8;
    const uint32_t kselB = (uint32_t)((lane >> 3) & 1) * 16;
    uint32_t boff[2];
    #pragma unroll
    for (int p = 0; p < 2; ++p)
        boff[p] = (uint32_t)((wn * 32 + p * 16 + rowB) * STB) + kselB;

    issue(0, 0); cp_commit();
    issue(1, 1); cp_commit();

    float acc[4][4][4] = {};

    for (int it = 0; it < KT; ++it) {
        cp_wait<1>();
        __syncthreads();

        const int nk = it + 2;
        if (nk < KT) issue(nk, nk % NSTAGE);
        cp_commit();

        const int cur = it % NSTAGE;
        const uint32_t abase = smem_u + (uint32_t)(cur * SSZ * 4);
        const uint32_t bbase = abase + (uint32_t)(TSZ * 4);

        #pragma unroll
        for (int ks = 0; ks < 4; ++ks) {
            const uint32_t kbyte = (uint32_t)(ks * 32);
            uint32_t af[4][4], bf[2][4];
            #pragma unroll
            for (int mt = 0; mt < 4; ++mt)
                ldsm_x4(af[mt], abase + aoff[mt] + kbyte);
            #pragma unroll
            for (int p = 0; p < 2; ++p)
                ldsm_x4(bf[p], bbase + boff[p] + kbyte);
            #pragma unroll
            for (int mt = 0; mt < 4; ++mt) {
                mma_fp16(acc[mt][0], af[mt], &bf[0][0]);
                mma_fp16(acc[mt][1], af[mt], &bf[0][2]);
                mma_fp16(acc[mt][2], af[mt], &bf[1][0]);
                mma_fp16(acc[mt][3], af[mt], &bf[1][2]);
            }
        }
    }

    #pragma unroll
    for (int mt = 0; mt < 4; ++mt) {
        const int gm = m0 + wm * 64 + mt * 16 + g;
        #pragma unroll
        for (int nt = 0; nt < 4; ++nt) {
            const int gn = n0 + wn * 32 + nt * 8 + 2 * tg;
            if (gn < N) {
                const float b0 = bias[gn], b1 = bias[gn + 1];
                float2 v0 = make_float2(acc[mt][nt][0] + b0, acc[mt][nt][1] + b1);
                float2 v1 = make_float2(acc[mt][nt][2] + b0, acc[mt][nt][3] + b1);
                const size_t i0 = (size_t)gm * N + gn;
                const size_t i1 = (size_t)(gm + 8) * N + gn;
                if (R) {
                    v0.x += R[i0];     v0.y += R[i0 + 1];
                    v1.x += R[i1];     v1.y += R[i1 + 1];
                }
                if (Rh) {
                    const float2 r0 = __half22float2(*(const __half2*)&Rh[i0]);
                    const float2 r1 = __half22float2(*(const __half2*)&Rh[i1]);
                    v0.x += r0.x; v0.y += r0.y;
                    v1.x += r1.x; v1.y += r1.y;
                }
                if (C) {
                    *(float2*)&C[i0] = v0;
                    *(float2*)&C[i1] = v1;
                }
                if (Ch) {
                    *(__half2*)&Ch[i0] = __floats2half2_rn(v0.x, v0.y);
                    *(__half2*)&Ch[i1] = __floats2half2_rn(v1.x, v1.y);
                }
            }
        }
    }
}

// standalone GEMM launch
__global__ __launch_bounds__(256, 2)
void gemm_fp16_kernel(const __half* __restrict__ A, const __half* __restrict__ WT,
                      const float* __restrict__ bias, const float* __restrict__ R,
                      const __half* __restrict__ Rh,
                      float* __restrict__ C, __half* __restrict__ Ch,
                      int M, int N, int K) {
    gemm_body(A, WT, bias, R, Rh, C, Ch, M, N, K, blockIdx.x, blockIdx.y);
}

// merged dual GEMM: blocks [0, nb0) -> GEMM0, rest -> GEMM1 (1D grid)
__global__ __launch_bounds__(256, 2)
void gemm2_fp16_kernel(const __half* A0, const __half* W0, const float* b0,
                       float* C0, __half* Ch0, int M0, int N0, int K0, int nb0, int gx0,
                       const __half* A1, const __half* W1, const float* b1,
                       float* C1, __half* Ch1, int M1, int N1, int K1, int gx1) {
    int bid = blockIdx.x;
    if (bid < nb0) {
        gemm_body(A0, W0, b0, nullptr, nullptr, C0, Ch0, M0, N0, K0,
                  bid % gx0, bid / gx0);
    } else {
        bid -= nb0;
        gemm_body(A1, W1, b1, nullptr, nullptr, C1, Ch1, M1, N1, K1,
                  bid % gx1, bid / gx1);
    }
}

// ---------------- LayerNorm bodies ------------------------------------------
__device__ __forceinline__ void ln_finish(float s, float ss, int t,
                                          float& mean, float& inv) {
    __shared__ float red0[6], red1[6];
    #pragma unroll
    for (int o = 16; o; o >>= 1) {
        s  += __shfl_down_sync(0xffffffffu, s,  o);
        ss += __shfl_down_sync(0xffffffffu, ss, o);
    }
    if ((t & 31) == 0) { red0[t >> 5] = s; red1[t >> 5] = ss; }
    __syncthreads();
    float st = 0.f, sst = 0.f;
    #pragma unroll
    for (int i = 0; i < 6; ++i) { st += red0[i]; sst += red1[i]; }
    mean = st * (1.f / CC);
    const float var = sst * (1.f / CC) - mean * mean;
    inv = rsqrtf(var + 1e-6f);
}

__device__ __forceinline__ void ln_row(const float* __restrict__ xr,
                                       const float* __restrict__ w,
                                       const float* __restrict__ b,
                                       __half* __restrict__ yr, int t) {
    const float4 v = ((const float4*)xr)[t];
    float mean, inv;
    ln_finish(v.x + v.y + v.z + v.w,
              v.x*v.x + v.y*v.y + v.z*v.z + v.w*v.w, t, mean, inv);
    const float4 wv = ((const float4*)w)[t];
    const float4 bv = ((const float4*)b)[t];
    __half2 h0 = __floats2half2_rn((v.x - mean) * inv * wv.x + bv.x,
                                   (v.y - mean) * inv * wv.y + bv.y);
    __half2 h1 = __floats2half2_rn((v.z - mean) * inv * wv.z + bv.z,
                                   (v.w - mean) * inv * wv.w + bv.w);
    uint2 o2 = make_uint2(*(uint32_t*)&h0, *(uint32_t*)&h1);
    *(uint2*)&yr[t * 4] = o2;
}

// fused dual LN: rows [0,MQ) -> query/qn, rows [MQ,MQ+MF) -> feat/fn
__global__ void ln2_kernel(const float* __restrict__ q, const float* __restrict__ qw,
                           const float* __restrict__ qb, __half* __restrict__ qy,
                           const float* __restrict__ f, const float* __restrict__ fw,
                           const float* __restrict__ fb, __half* __restrict__ fy) {
    int row = blockIdx.x;
    if (row < MQ) {
        ln_row(q + (size_t)row * CC, qw, qb, qy + (size_t)row * CC, threadIdx.x);
    } else {
        row -= MQ;
        ln_row(f + (size_t)row * CC, fw, fb, fy + (size_t)row * CC, threadIdx.x);
    }
}

// LN with fp16 input (for ffn LN over q2h)
__global__ void ln_h_kernel(const __half* __restrict__ x, const float* __restrict__ w,
                            const float* __restrict__ b, __half* __restrict__ y) {
    const int row = blockIdx.x;
    const int t = threadIdx.x;
    const uint2 raw = *(const uint2*)&x[(size_t)row * CC + t * 4];
    const float2 f0 = __half22float2(*(const __half2*)&raw.x);
    const float2 f1 = __half22float2(*(const __half2*)&raw.y);
    float mean, inv;
    ln_finish(f0.x + f0.y + f1.x + f1.y,
              f0.x*f0.x + f0.y*f0.y + f1.x*f1.x + f1.y*f1.y, t, mean, inv);
    const float4 wv = ((const float4*)w)[t];
    const float4 bv = ((const float4*)b)[t];
    __half2 h0 = __floats2half2_rn((f0.x - mean) * inv * wv.x + bv.x,
                                   (f0.y - mean) * inv * wv.y + bv.y);
    __half2 h1 = __floats2half2_rn((f1.x - mean) * inv * wv.z + bv.z,
                                   (f1.y - mean) * inv * wv.w + bv.w);
    uint2 o2 = make_uint2(*(uint32_t*)&h0, *(uint32_t*)&h1);
    *(uint2*)&y[(size_t)row * CC + t * 4] = o2;
}

// ---------------- fused weight prep: 4 transposes + pack, one launch --------
__device__ __forceinline__ void transp_tile(const float* __restrict__ src,
                                            __half* __restrict__ dst,
                                            int K, int N, int bx, int by, int t) {
    __shared__ float tile[32][33];
    const int kb = by * 32, nb = bx * 32;
    const int tx = t & 31, ty = t >> 5;
    #pragma unroll
    for (int i = 0; i < 32; i += 8) {
        const int k = kb + ty + i, n = nb + tx;
        tile[ty + i][tx] = (k < K && n < N) ? src[(size_t)k * N + n] : 0.f;
    }
    __syncthreads();
    #pragma unroll
    for (int i = 0; i < 32; i += 8) {
        const int n = nb + ty + i, k = kb + tx;
        if (n < N && k < K) dst[(size_t)n * K + k] = __float2half_rn(tile[tx][ty + i]);
    }
}

#define PREP_A 576
#define PREP_B 1152
#define PREP_C 1296
#define PREP_D 1440
#define PREP_E 1656
__global__ void prep_kernel(const float* __restrict__ vp_w,  __half* __restrict__ vpT,
                            const float* __restrict__ op_w,  __half* __restrict__ opT,
                            const float* __restrict__ fc1_w, __half* __restrict__ fc1T,
                            const float* __restrict__ fc2_w, __half* __restrict__ fc2T,
                            const float* __restrict__ so_w, const float* __restrict__ so_b,
                            const float* __restrict__ aw_w, const float* __restrict__ aw_b,
                            __half* __restrict__ w72T, float* __restrict__ b72) {
    const int b = blockIdx.x;
    const int t = threadIdx.x;
    if (b < PREP_A) {
        transp_tile(vp_w, vpT, CC, CC, b % 24, b / 24, t);
    } else if (b < PREP_B) {
        const int c = b - PREP_A;
        transp_tile(op_w, opT, CC, CC, c % 24, c / 24, t);
    } else if (b < PREP_C) {
        const int c = b - PREP_B;
        transp_tile(fc1_w, fc1T, CC, HID, c % 6, c / 6, t);
    } else if (b < PREP_D) {
        const int c = b - PREP_C;
        transp_tile(fc2_w, fc2T, HID, CC, c % 24, c / 24, t);
    } else {
        const int i = (b - PREP_D) * 256 + t;
        if (i < NOA * CC) {
            const int n = i / CC, k = i % CC;
            const float v = (n < 48) ? so_w[k * 48 + n] : aw_w[k * 24 + (n - 48)];
            w72T[i] = __float2half_rn(v);
        }
        if (i < NOA) b72[i] = (i < 48) ? so_b[i] : aw_b[i - 48];
    }
}

// ------- softmax(attn weights) + bilinear sample + weighted reduce ---------
// One block per 2 queries; 192 threads = 2 x 96, each thread owns 8 channels.
// Corner accumulation in half2 (HFMA2), per-point upconvert to fp32.
__global__ void sample_kernel(const float* __restrict__ refp, __half* __restrict__ attn) {
    const int q0 = blockIdx.x * 2;
    __shared__ __half2 cw[2][NH * NP][4];
    __shared__ int     ci[2][NH * NP][4];
    __shared__ float   lg[2][NH * NP];
    const int t = threadIdx.x;
    if (t < 2 * NH * NP) {
        const int qi = t / (NH * NP), j = t % (NH * NP);
        lg[qi][j] = g_oa[(size_t)(q0 + qi) * NOA + 48 + j];
    }
    __syncthreads();
    if (t < 2 * NH * NP) {
        const int qi = t / (NH * NP), j = t % (NH * NP);
        const int q = q0 + qi;
        const int h = j >> 2;
        float l0 = lg[qi][h*4+0], l1 = lg[qi][h*4+1], l2 = lg[qi][h*4+2], l3 = lg[qi][h*4+3];
        float m  = fmaxf(fmaxf(l0, l1), fmaxf(l2, l3));
        float e0 = __expf(l0-m), e1 = __expf(l1-m), e2 = __expf(l2-m), e3 = __expf(l3-m);
        float aw = __expf(lg[qi][j]-m) / (e0 + e1 + e2 + e3);
        float rx = refp[(size_t)q * 2 + 0];
        float ry = refp[(size_t)q * 2 + 1];
        float ox = g_oa[(size_t)q * NOA + j*2 + 0];
        float oy = g_oa[(size_t)q * NOA + j*2 + 1];
        float x = (rx + ox * (1.f / WL)) * WL - 0.5f;
        float y = (ry + oy * (1.f / HL)) * HL - 0.5f;
        float x0f = floorf(x), y0f = floorf(y);
        float wx = x - x0f, wy = y - y0f;
        int x0 = (int)x0f, y0 = (int)y0f;
        float ws[4] = {(1.f-wy)*(1.f-wx), (1.f-wy)*wx, wy*(1.f-wx), wy*wx};
        const int dys[4] = {0,0,1,1}, dxs[4] = {0,1,0,1};
        #pragma unroll
        for (int c2 = 0; c2 < 4; c2++) {
            int xi = x0 + dxs[c2], yi = y0 + dys[c2];
            bool valid = (xi >= 0) && (xi < WL) && (yi >= 0) && (yi < HL);
            ci[qi][j][c2] = valid ? (yi * WL + xi) : -1;
            float wv = valid ? ws[c2] * aw : 0.f;
            cw[qi][j][c2] = __float2half2_rn(wv);
        }
    }
    __syncthreads();
    const int qi = t / 96;           // query within pair
    const int tc = t % 96;           // channel group: halves tc*8 .. tc*8+7
    const int h  = tc >> 4;          // head = (tc*8)/128
    const int q  = q0 + qi;
    const __half* vb = g_val16 + (size_t)(q / LQ) * LIN * CC + tc * 8;
    float a0 = 0.f, a1 = 0.f, a2 = 0.f, a3 = 0.f;
    float a4 = 0.f, a5 = 0.f, a6 = 0.f, a7 = 0.f;
    #pragma unroll
    for (int j = 0; j < NP; ++j) {
        const __half2 zero2 = __float2half2_rn(0.f);
        __half2 p0 = zero2, p1 = zero2, p2 = zero2, p3 = zero2;
        #pragma unroll
        for (int c2 = 0; c2 < 4; ++c2) {
            const int idx = ci[qi][h * NP + j][c2];
            if (idx >= 0) {
                const __half2 w2 = cw[qi][h * NP + j][c2];
                const uint4 raw = *(const uint4*)&vb[(size_t)idx * CC];
                p0 = __hfma2(*(const __half2*)&raw.x, w2, p0);
                p1 = __hfma2(*(const __half2*)&raw.y, w2, p1);
                p2 = __hfma2(*(const __half2*)&raw.z, w2, p2);
                p3 = __hfma2(*(const __half2*)&raw.w, w2, p3);
            }
        }
        const float2 f0 = __half22float2(p0);
        const float2 f1 = __half22float2(p1);
        const float2 f2 = __half22float2(p2);
        const float2 f3 = __half22float2(p3);
        a0 += f0.x; a1 += f0.y; a2 += f1.x; a3 += f1.y;
        a4 += f2.x; a5 += f2.y; a6 += f3.x; a7 += f3.y;
    }
    __half2 h0 = __floats2half2_rn(a0, a1);
    __half2 h1 = __floats2half2_rn(a2, a3);
    __half2 h2 = __floats2half2_rn(a4, a5);
    __half2 h3 = __floats2half2_rn(a6, a7);
    uint4 o4 = make_uint4(*(uint32_t*)&h0, *(uint32_t*)&h1,
                          *(uint32_t*)&h2, *(uint32_t*)&h3);
    *(uint4*)&attn[(size_t)q * CC + tc * 8] = o4;
}

// ---------- depthwise 3x3 conv (SAME, zero pad) + bias + exact GELU --------
__global__ void dwconv_gelu_kernel(const __half* __restrict__ x, const float* __restrict__ w,
                                   const float* __restrict__ bias, __half* __restrict__ y) {
    const int c  = threadIdx.x;
    const float bb = bias[c];
    float wr[9];
    #pragma unroll
    for (int i = 0; i < 9; ++i) wr[i] = w[c * 9 + i];
    #pragma unroll
    for (int sub = 0; sub < 4; ++sub) {
        const int pg = blockIdx.x * 4 + sub;
        const int b    = pg / LQ;
        const int rem  = pg % LQ;
        const int chunk = rem / (HH * WW);
        const int pix   = rem % (HH * WW);
        const int py = pix >> 5, px = pix & 31;
        const __half* xb = x + ((size_t)b * LQ + (size_t)chunk * HH * WW) * HID;
        float acc = bb;
        #pragma unroll
        for (int dy = -1; dy <= 1; dy++) {
            int yy = py + dy;
            if (yy < 0 || yy >= HH) continue;
            #pragma unroll
            for (int dx = -1; dx <= 1; dx++) {
                int xx = px + dx;
                if (xx < 0 || xx >= WW) continue;
                acc += __half2float(xb[(size_t)(yy * WW + xx) * HID + c])
                       * wr[(dy + 1) * 3 + (dx + 1)];
            }
        }
        float gl = 0.5f * acc * (1.f + erff(acc * 0.70710678118654752f));
        y[(size_t)pg * HID + c] = __float2half_rn(gl);
    }
}

// ---------------------------------------------------------------------------
static inline void launch_gemm(const __half* A, const __half* WT, const float* bias,
                               const float* R, const __half* Rh,
                               float* C, __half* Ch, int M, int N, int K) {
    dim3 grid((N + 127) / 128, M / 128);
    gemm_fp16_kernel<<<grid, 256, GEMM_SMEM>>>(A, WT, bias, R, Rh, C, Ch, M, N, K);
}

extern "C" void kernel_launch(void* const* d_in, const int* in_sizes, int n_in,
                              void* d_out, int out_size) {
    const float* query = (const float*)d_in[0];
    const float* refp  = (const float*)d_in[1];
    const float* feat  = (const float*)d_in[2];
    const float* qn_w = (const float*)d_in[7];
    const float* qn_b = (const float*)d_in[8];
    const float* fn_w = (const float*)d_in[9];
    const float* fn_b = (const float*)d_in[10];
    const float* so_w = (const float*)d_in[11];
    const float* so_b = (const float*)d_in[12];
    const float* aw_w = (const float*)d_in[13];
    const float* aw_b = (const float*)d_in[14];
    const float* vp_w = (const float*)d_in[15];
    const float* vp_b = (const float*)d_in[16];
    const float* op_w = (const float*)d_in[17];
    const float* op_b = (const float*)d_in[18];
    const float* ffn_w = (const float*)d_in[19];
    const float* ffn_b = (const float*)d_in[20];
    const float* fc1_w = (const float*)d_in[21];
    const float* fc1_b = (const float*)d_in[22];
    const float* dw_w  = (const float*)d_in[23];
    const float* dw_b  = (const float*)d_in[24];
    const float* fc2_w = (const float*)d_in[25];
    const float* fc2_b = (const float*)d_in[26];
    float* out = (float*)d_out;

    __half *p_qln16, *p_fln16, *p_val16, *p_attn16, *p_x1h, *p_x2h, *p_q2h;
    __half *p_vpT, *p_opT, *p_fc1T, *p_fc2T, *p_w72T;
    float *p_oa, *p_b72;
    cudaGetSymbolAddress((void**)&p_qln16,  g_qln16);
    cudaGetSymbolAddress((void**)&p_fln16,  g_fln16);
    cudaGetSymbolAddress((void**)&p_val16,  g_val16);
    cudaGetSymbolAddress((void**)&p_attn16, g_attn16);
    cudaGetSymbolAddress((void**)&p_x1h,    g_x1h);
    cudaGetSymbolAddress((void**)&p_x2h,    g_x2h);
    cudaGetSymbolAddress((void**)&p_q2h,    g_q2h);
    cudaGetSymbolAddress((void**)&p_vpT,    g_vpT16);
    cudaGetSymbolAddress((void**)&p_opT,    g_opT16);
    cudaGetSymbolAddress((void**)&p_fc1T,   g_fc1T16);
    cudaGetSymbolAddress((void**)&p_fc2T,   g_fc2T16);
    cudaGetSymbolAddress((void**)&p_w72T,   g_w72T16);
    cudaGetSymbolAddress((void**)&p_oa,     g_oa);
    cudaGetSymbolAddress((void**)&p_b72,    g_b72);

    cudaFuncSetAttribute(gemm_fp16_kernel, cudaFuncAttributeMaxDynamicSharedMemorySize, GEMM_SMEM);
    cudaFuncSetAttribute(gemm2_fp16_kernel, cudaFuncAttributeMaxDynamicSharedMemorySize, GEMM_SMEM);

    // 0. fused weight prep (4 transposes + pack) in ONE launch
    prep_kernel<<<PREP_E, 256>>>(vp_w, p_vpT, op_w, p_opT, fc1_w, p_fc1T,
                                 fc2_w, p_fc2T, so_w, so_b, aw_w, aw_b, p_w72T, p_b72);

    // 1. both LayerNorms in ONE launch (fp32 in -> fp16 out)
    ln2_kernel<<<MQ + MF, 192>>>(query, qn_w, qn_b, p_qln16,
                                 feat,  fn_w, fn_b, p_fln16);

    // 2+3. MERGED: oa projection (192 blocks) + value GEMM (1536 blocks)
    {
        const int gx0 = 1,  nb0 = MQ / 128;              // oa:    1 x 192
        const int gx1 = CC / 128;                        // value: 6 x 256
        const int nb1 = gx1 * (MF / 128);                // 1536
        gemm2_fp16_kernel<<<nb0 + nb1, 256, GEMM_SMEM>>>(
            p_qln16, p_w72T, p_b72, p_oa, nullptr, MQ, NOA, CC, nb0, gx0,
            p_fln16, p_vpT,  vp_b,  nullptr, p_val16, MF, CC,  CC, gx1);
    }

    // 4. softmax + bilinear sample + head-reduce (HFMA2 corners, uint4 gathers)
    sample_kernel<<<MQ / 2, 192>>>(refp, p_attn16);

    // 5. output projection + residual(query fp32) -> q2 HALF  (24576 x 768 x 768)
    launch_gemm(p_attn16, p_opT, op_b, query, nullptr, nullptr, p_q2h, MQ, CC, CC);

    // 6. ConvFFN (LN over half q2, fc1 -> half, dwconv, fc2 + half residual -> out)
    ln_h_kernel<<<MQ, 192>>>(p_q2h, ffn_w, ffn_b, p_qln16);
    launch_gemm(p_qln16, p_fc1T, fc1_b, nullptr, nullptr, nullptr, p_x1h, MQ, HID, CC);
    dwconv_gelu_kernel<<<MQ / 4, HID>>>(p_x1h, dw_w, dw_b, p_x2h);
    launch_gemm(p_x2h, p_fc2T, fc2_b, nullptr, p_q2h, out, nullptr, MQ, CC, HID);
}

// round 16
// speedup vs baseline: 1.0222x; 1.0222x over previous
#include <cuda_runtime.h>
#include <cuda_fp16.h>
#include <math.h>
#include <stdint.h>

// ---------------- problem constants (fixed by setup_inputs) ----------------
#define BB   8
#define LQ   3072
#define CC   768
#define LIN  4096          // 64*64 feature tokens
#define HL   64
#define WL   64
#define NH   6
#define NP   4
#define HID  192
#define HH   32
#define WW   32
#define MQ   (BB*LQ)       // 24576
#define MF   (BB*LIN)      // 32768
#define NOA  72            // 48 offs + 24 attn logits, fused

// ---------------- scratch (device globals; no allocs allowed) --------------
__device__ __half g_qln16 [MQ*CC];
__device__ __half g_fln16 [MF*CC];
__device__ __half g_val16 [MF*CC];
__device__ __half g_attn16[MQ*CC];
__device__ __half g_x1h   [MQ*HID];
__device__ __half g_x2h   [MQ*HID];
__device__ __half g_q2h   [MQ*CC];
__device__ float  g_oa    [MQ*NOA];
// transposed fp16 weights [N][K]
__device__ __half g_vpT16 [CC*CC];
__device__ __half g_opT16 [CC*CC];
__device__ __half g_fc1T16[HID*CC];
__device__ __half g_fc2T16[CC*HID];
__device__ __half g_w72T16[NOA*CC];
__device__ float  g_b72   [NOA];

// ---------------- mma / ldmatrix / cp.async helpers -------------------------
__device__ __forceinline__ void mma_fp16(float* d, const uint32_t* a, const uint32_t* b) {
    asm volatile(
        "mma.sync.aligned.m16n8k16.row.col.f32.f16.f16.f32 "
        "{%0,%1,%2,%3}, {%4,%5,%6,%7}, {%8,%9}, {%0,%1,%2,%3};\n"
        : "+f"(d[0]), "+f"(d[1]), "+f"(d[2]), "+f"(d[3])
        : "r"(a[0]), "r"(a[1]), "r"(a[2]), "r"(a[3]), "r"(b[0]), "r"(b[1]));
}
__device__ __forceinline__ void ldsm_x4(uint32_t* r, uint32_t addr) {
    asm volatile("ldmatrix.sync.aligned.m8n8.x4.shared.b16 {%0,%1,%2,%3}, [%4];"
                 : "=r"(r[0]), "=r"(r[1]), "=r"(r[2]), "=r"(r[3]) : "r"(addr));
}
__device__ __forceinline__ void cp16(uint32_t dst, const void* src, bool valid) {
    int sz = valid ? 16 : 0;
    asm volatile("cp.async.cg.shared.global [%0], [%1], 16, %2;\n"
                 :: "r"(dst), "l"(src), "r"(sz));
}
__device__ __forceinline__ void cp_commit() { asm volatile("cp.async.commit_group;\n"); }
template <int N> __device__ __forceinline__ void cp_wait() {
    asm volatile("cp.async.wait_group %0;\n" :: "n"(N));
}

// ---------------- fp16 tensor-core GEMM body --------------------------------
#define ST 36                 // row stride in u32 (32 data + 4 pad) -> conflict-free
#define STB (ST*4)            // 144 bytes
#define TSZ (128 * ST)        // one tile (A or B) in u32 = 4608
#define SSZ (2 * TSZ)         // stage = A + B = 9216 u32
#define NSTAGE 3
#define GEMM_SMEM (NSTAGE * SSZ * 4)   // 110,592 B

__device__ __forceinline__ void gemm_body(
        const __half* __restrict__ A, const __half* __restrict__ WT,
        const float* __restrict__ bias, const float* __restrict__ R,
        const __half* __restrict__ Rh,
        float* __restrict__ C, __half* __restrict__ Ch,
        int M, int N, int K, int bx, int by) {
    extern __shared__ uint32_t sm[];

    const int t    = threadIdx.x;
    const int lane = t & 31;
    const int g    = lane >> 2;
    const int tg   = lane & 3;
    const int wid  = t >> 5;
    const int wm   = wid & 1;
    const int wn   = wid >> 1;

    const int m0 = by * 128;
    const int n0 = bx * 128;

    const int sr = t >> 3;
    const int sc = (t & 7) * 8;
    const uint32_t smem_u = (uint32_t)__cvta_generic_to_shared(sm);
    const uint32_t soff = (uint32_t)(sr * STB + (t & 7) * 16);

    const __half* Abase = A + (size_t)(m0 + sr) * K + sc;
    const __half* WTbase = WT + (size_t)sr * K + sc;

    const int KT = K >> 6;

    auto issue = [&](int ck, int s) {
        const uint32_t sb = smem_u + (uint32_t)(s * SSZ * 4);
        const __half* Ap = Abase + ck * 64;
        const __half* Bp = WTbase + ck * 64;
        #pragma unroll
        for (int j = 0; j < 4; ++j) {
            cp16(sb + soff + (uint32_t)(32 * j * STB),
                 Ap + (size_t)(32 * j) * K, true);
            const int nr = n0 + sr + 32 * j;
            cp16(sb + (uint32_t)(TSZ * 4) + soff + (uint32_t)(32 * j * STB),
                 Bp + (size_t)(n0 + 32 * j) * K, nr < N);
        }
    };

    const int rowA  = (lane & 7) + ((lane >> 3) & 1) * 8;
    const uint32_t kselA = (uint32_t)(lane >> 4) * 16;
    uint32_t aoff[4];
    #pragma unroll
    for (int mt = 0; mt < 4; ++mt)
        aoff[mt] = (uint32_t)((wm * 64 + mt * 16 + rowA) * STB) + kselA;
    const int rowB  = (lane & 7) + ((lane >> 4) & 1) * 8;
    const uint32_t kselB = (uint32_t)((lane >> 3) & 1) * 16;
    uint32_t boff[2];
    #pragma unroll
    for (int p = 0; p < 2; ++p)
        boff[p] = (uint32_t)((wn * 32 + p * 16 + rowB) * STB) + kselB;

    issue(0, 0); cp_commit();
    issue(1, 1); cp_commit();

    float acc[4][4][4] = {};

    for (int it = 0; it < KT; ++it) {
        cp_wait<1>();
        __syncthreads();

        const int nk = it + 2;
        if (nk < KT) issue(nk, nk % NSTAGE);
        cp_commit();

        const int cur = it % NSTAGE;
        const uint32_t abase = smem_u + (uint32_t)(cur * SSZ * 4);
        const uint32_t bbase = abase + (uint32_t)(TSZ * 4);

        #pragma unroll
        for (int ks = 0; ks < 4; ++ks) {
            const uint32_t kbyte = (uint32_t)(ks * 32);
            uint32_t af[4][4], bf[2][4];
            #pragma unroll
            for (int mt = 0; mt < 4; ++mt)
                ldsm_x4(af[mt], abase + aoff[mt] + kbyte);
            #pragma unroll
            for (int p = 0; p < 2; ++p)
                ldsm_x4(bf[p], bbase + boff[p] + kbyte);
            #pragma unroll
            for (int mt = 0; mt < 4; ++mt) {
                mma_fp16(acc[mt][0], af[mt], &bf[0][0]);
                mma_fp16(acc[mt][1], af[mt], &bf[0][2]);
                mma_fp16(acc[mt][2], af[mt], &bf[1][0]);
                mma_fp16(acc[mt][3], af[mt], &bf[1][2]);
            }
        }
    }

    #pragma unroll
    for (int mt = 0; mt < 4; ++mt) {
        const int gm = m0 + wm * 64 + mt * 16 + g;
        #pragma unroll
        for (int nt = 0; nt < 4; ++nt) {
            const int gn = n0 + wn * 32 + nt * 8 + 2 * tg;
            if (gn < N) {
                const float b0 = bias[gn], b1 = bias[gn + 1];
                float2 v0 = make_float2(acc[mt][nt][0] + b0, acc[mt][nt][1] + b1);
                float2 v1 = make_float2(acc[mt][nt][2] + b0, acc[mt][nt][3] + b1);
                const size_t i0 = (size_t)gm * N + gn;
                const size_t i1 = (size_t)(gm + 8) * N + gn;
                if (R) {
                    v0.x += R[i0];     v0.y += R[i0 + 1];
                    v1.x += R[i1];     v1.y += R[i1 + 1];
                }
                if (Rh) {
                    const float2 r0 = __half22float2(*(const __half2*)&Rh[i0]);
                    const float2 r1 = __half22float2(*(const __half2*)&Rh[i1]);
                    v0.x += r0.x; v0.y += r0.y;
                    v1.x += r1.x; v1.y += r1.y;
                }
                if (C) {
                    *(float2*)&C[i0] = v0;
                    *(float2*)&C[i1] = v1;
                }
                if (Ch) {
                    *(__half2*)&Ch[i0] = __floats2half2_rn(v0.x, v0.y);
                    *(__half2*)&Ch[i1] = __floats2half2_rn(v1.x, v1.y);
                }
            }
        }
    }
}

// standalone GEMM launch
__global__ __launch_bounds__(256, 2)
void gemm_fp16_kernel(const __half* __restrict__ A, const __half* __restrict__ WT,
                      const float* __restrict__ bias, const float* __restrict__ R,
                      const __half* __restrict__ Rh,
                      float* __restrict__ C, __half* __restrict__ Ch,
                      int M, int N, int K) {
    gemm_body(A, WT, bias, R, Rh, C, Ch, M, N, K, blockIdx.x, blockIdx.y);
}

// merged dual GEMM: blocks [0, nb0) -> GEMM0, rest -> GEMM1 (1D grid)
__global__ __launch_bounds__(256, 2)
void gemm2_fp16_kernel(const __half* A0, const __half* W0, const float* b0,
                       float* C0, __half* Ch0, int M0, int N0, int K0, int nb0, int gx0,
                       const __half* A1, const __half* W1, const float* b1,
                       float* C1, __half* Ch1, int M1, int N1, int K1, int gx1) {
    int bid = blockIdx.x;
    if (bid < nb0) {
        gemm_body(A0, W0, b0, nullptr, nullptr, C0, Ch0, M0, N0, K0,
                  bid % gx0, bid / gx0);
    } else {
        bid -= nb0;
        gemm_body(A1, W1, b1, nullptr, nullptr, C1, Ch1, M1, N1, K1,
                  bid % gx1, bid / gx1);
    }
}

// ---------------- LayerNorm bodies ------------------------------------------
__device__ __forceinline__ void ln_finish(float s, float ss, int t,
                                          float& mean, float& inv) {
    __shared__ float red0[6], red1[6];
    #pragma unroll
    for (int o = 16; o; o >>= 1) {
        s  += __shfl_down_sync(0xffffffffu, s,  o);
        ss += __shfl_down_sync(0xffffffffu, ss, o);
    }
    if ((t & 31) == 0) { red0[t >> 5] = s; red1[t >> 5] = ss; }
    __syncthreads();
    float st = 0.f, sst = 0.f;
    #pragma unroll
    for (int i = 0; i < 6; ++i) { st += red0[i]; sst += red1[i]; }
    mean = st * (1.f / CC);
    const float var = sst * (1.f / CC) - mean * mean;
    inv = rsqrtf(var + 1e-6f);
}

__device__ __forceinline__ void ln_row(const float* __restrict__ xr,
                                       const float* __restrict__ w,
                                       const float* __restrict__ b,
                                       __half* __restrict__ yr, int t) {
    const float4 v = ((const float4*)xr)[t];
    float mean, inv;
    ln_finish(v.x + v.y + v.z + v.w,
              v.x*v.x + v.y*v.y + v.z*v.z + v.w*v.w, t, mean, inv);
    const float4 wv = ((const float4*)w)[t];
    const float4 bv = ((const float4*)b)[t];
    __half2 h0 = __floats2half2_rn((v.x - mean) * inv * wv.x + bv.x,
                                   (v.y - mean) * inv * wv.y + bv.y);
    __half2 h1 = __floats2half2_rn((v.z - mean) * inv * wv.z + bv.z,
                                   (v.w - mean) * inv * wv.w + bv.w);
    uint2 o2 = make_uint2(*(uint32_t*)&h0, *(uint32_t*)&h1);
    *(uint2*)&yr[t * 4] = o2;
}

// fused dual LN: rows [0,MQ) -> query/qn, rows [MQ,MQ+MF) -> feat/fn
__global__ void ln2_kernel(const float* __restrict__ q, const float* __restrict__ qw,
                           const float* __restrict__ qb, __half* __restrict__ qy,
                           const float* __restrict__ f, const float* __restrict__ fw,
                           const float* __restrict__ fb, __half* __restrict__ fy) {
    int row = blockIdx.x;
    if (row < MQ) {
        ln_row(q + (size_t)row * CC, qw, qb, qy + (size_t)row * CC, threadIdx.x);
    } else {
        row -= MQ;
        ln_row(f + (size_t)row * CC, fw, fb, fy + (size_t)row * CC, threadIdx.x);
    }
}

// LN with fp16 input (for ffn LN over q2h)
__global__ void ln_h_kernel(const __half* __restrict__ x, const float* __restrict__ w,
                            const float* __restrict__ b, __half* __restrict__ y) {
    const int row = blockIdx.x;
    const int t = threadIdx.x;
    const uint2 raw = *(const uint2*)&x[(size_t)row * CC + t * 4];
    const float2 f0 = __half22float2(*(const __half2*)&raw.x);
    const float2 f1 = __half22float2(*(const __half2*)&raw.y);
    float mean, inv;
    ln_finish(f0.x + f0.y + f1.x + f1.y,
              f0.x*f0.x + f0.y*f0.y + f1.x*f1.x + f1.y*f1.y, t, mean, inv);
    const float4 wv = ((const float4*)w)[t];
    const float4 bv = ((const float4*)b)[t];
    __half2 h0 = __floats2half2_rn((f0.x - mean) * inv * wv.x + bv.x,
                                   (f0.y - mean) * inv * wv.y + bv.y);
    __half2 h1 = __floats2half2_rn((f1.x - mean) * inv * wv.z + bv.z,
                                   (f1.y - mean) * inv * wv.w + bv.w);
    uint2 o2 = make_uint2(*(uint32_t*)&h0, *(uint32_t*)&h1);
    *(uint2*)&y[(size_t)row * CC + t * 4] = o2;
}

// ---------------- fused weight prep: 4 transposes + pack, one launch --------
__device__ __forceinline__ void transp_tile(const float* __restrict__ src,
                                            __half* __restrict__ dst,
                                            int K, int N, int bx, int by, int t) {
    __shared__ float tile[32][33];
    const int kb = by * 32, nb = bx * 32;
    const int tx = t & 31, ty = t >> 5;
    #pragma unroll
    for (int i = 0; i < 32; i += 8) {
        const int k = kb + ty + i, n = nb + tx;
        tile[ty + i][tx] = (k < K && n < N) ? src[(size_t)k * N + n] : 0.f;
    }
    __syncthreads();
    #pragma unroll
    for (int i = 0; i < 32; i += 8) {
        const int n = nb + ty + i, k = kb + tx;
        if (n < N && k < K) dst[(size_t)n * K + k] = __float2half_rn(tile[tx][ty + i]);
    }
}

#define PREP_A 576
#define PREP_B 1152
#define PREP_C 1296
#define PREP_D 1440
#define PREP_E 1656
__global__ void prep_kernel(const float* __restrict__ vp_w,  __half* __restrict__ vpT,
                            const float* __restrict__ op_w,  __half* __restrict__ opT,
                            const float* __restrict__ fc1_w, __half* __restrict__ fc1T,
                            const float* __restrict__ fc2_w, __half* __restrict__ fc2T,
                            const float* __restrict__ so_w, const float* __restrict__ so_b,
                            const float* __restrict__ aw_w, const float* __restrict__ aw_b,
                            __half* __restrict__ w72T, float* __restrict__ b72) {
    const int b = blockIdx.x;
    const int t = threadIdx.x;
    if (b < PREP_A) {
        transp_tile(vp_w, vpT, CC, CC, b % 24, b / 24, t);
    } else if (b < PREP_B) {
        const int c = b - PREP_A;
        transp_tile(op_w, opT, CC, CC, c % 24, c / 24, t);
    } else if (b < PREP_C) {
        const int c = b - PREP_B;
        transp_tile(fc1_w, fc1T, CC, HID, c % 6, c / 6, t);
    } else if (b < PREP_D) {
        const int c = b - PREP_C;
        transp_tile(fc2_w, fc2T, HID, CC, c % 24, c / 24, t);
    } else {
        const int i = (b - PREP_D) * 256 + t;
        if (i < NOA * CC) {
            const int n = i / CC, k = i % CC;
            const float v = (n < 48) ? so_w[k * 48 + n] : aw_w[k * 24 + (n - 48)];
            w72T[i] = __float2half_rn(v);
        }
        if (i < NOA) b72[i] = (i < 48) ? so_b[i] : aw_b[i - 48];
    }
}

// ------- softmax(attn weights) + bilinear sample + weighted reduce ---------
// One block per 2 queries; 192 threads = 2 x 96, each thread owns 8 channels.
// Branchless gathers: invalid corners clamp to idx 0 with weight 0.
__global__ void sample_kernel(const float* __restrict__ refp, __half* __restrict__ attn) {
    const int q0 = blockIdx.x * 2;
    __shared__ float cw[2][NH * NP][4];
    __shared__ int   ci[2][NH * NP][4];
    __shared__ float lg[2][NH * NP];
    const int t = threadIdx.x;
    if (t < 2 * NH * NP) {
        const int qi = t / (NH * NP), j = t % (NH * NP);
        lg[qi][j] = g_oa[(size_t)(q0 + qi) * NOA + 48 + j];
    }
    __syncthreads();
    if (t < 2 * NH * NP) {
        const int qi = t / (NH * NP), j = t % (NH * NP);
        const int q = q0 + qi;
        const int h = j >> 2;
        float l0 = lg[qi][h*4+0], l1 = lg[qi][h*4+1], l2 = lg[qi][h*4+2], l3 = lg[qi][h*4+3];
        float m  = fmaxf(fmaxf(l0, l1), fmaxf(l2, l3));
        float e0 = __expf(l0-m), e1 = __expf(l1-m), e2 = __expf(l2-m), e3 = __expf(l3-m);
        float aw = __expf(lg[qi][j]-m) / (e0 + e1 + e2 + e3);
        float rx = refp[(size_t)q * 2 + 0];
        float ry = refp[(size_t)q * 2 + 1];
        float ox = g_oa[(size_t)q * NOA + j*2 + 0];
        float oy = g_oa[(size_t)q * NOA + j*2 + 1];
        float x = (rx + ox * (1.f / WL)) * WL - 0.5f;
        float y = (ry + oy * (1.f / HL)) * HL - 0.5f;
        float x0f = floorf(x), y0f = floorf(y);
        float wx = x - x0f, wy = y - y0f;
        int x0 = (int)x0f, y0 = (int)y0f;
        float ws[4] = {(1.f-wy)*(1.f-wx), (1.f-wy)*wx, wy*(1.f-wx), wy*wx};
        const int dys[4] = {0,0,1,1}, dxs[4] = {0,1,0,1};
        #pragma unroll
        for (int c2 = 0; c2 < 4; c2++) {
            int xi = x0 + dxs[c2], yi = y0 + dys[c2];
            bool valid = (xi >= 0) && (xi < WL) && (yi >= 0) && (yi < HL);
            ci[qi][j][c2] = valid ? (yi * WL + xi) : 0;       // clamp, not -1
            cw[qi][j][c2] = valid ? ws[c2] * aw : 0.f;        // weight nullifies
        }
    }
    __syncthreads();
    const int qi = t / 96;           // query within pair
    const int tc = t % 96;           // channel group: halves tc*8 .. tc*8+7
    const int h  = tc >> 4;          // head = (tc*8)/128
    const int q  = q0 + qi;
    const __half* vb = g_val16 + (size_t)(q / LQ) * LIN * CC + tc * 8;
    float a0 = 0.f, a1 = 0.f, a2 = 0.f, a3 = 0.f;
    float a4 = 0.f, a5 = 0.f, a6 = 0.f, a7 = 0.f;
    #pragma unroll
    for (int j = 0; j < NP; ++j)
        #pragma unroll
        for (int c2 = 0; c2 < 4; ++c2) {
            const int idx = ci[qi][h * NP + j][c2];
            const float wgt = cw[qi][h * NP + j][c2];
            const uint4 raw = *(const uint4*)&vb[(size_t)idx * CC];
            const float2 f0 = __half22float2(*(const __half2*)&raw.x);
            const float2 f1 = __half22float2(*(const __half2*)&raw.y);
            const float2 f2 = __half22float2(*(const __half2*)&raw.z);
            const float2 f3 = __half22float2(*(const __half2*)&raw.w);
            a0 += f0.x * wgt; a1 += f0.y * wgt;
            a2 += f1.x * wgt; a3 += f1.y * wgt;
            a4 += f2.x * wgt; a5 += f2.y * wgt;
            a6 += f3.x * wgt; a7 += f3.y * wgt;
        }
    __half2 h0 = __floats2half2_rn(a0, a1);
    __half2 h1 = __floats2half2_rn(a2, a3);
    __half2 h2 = __floats2half2_rn(a4, a5);
    __half2 h3 = __floats2half2_rn(a6, a7);
    uint4 o4 = make_uint4(*(uint32_t*)&h0, *(uint32_t*)&h1,
                          *(uint32_t*)&h2, *(uint32_t*)&h3);
    *(uint4*)&attn[(size_t)q * CC + tc * 8] = o4;
}

// ---------- depthwise 3x3 conv (SAME, zero pad) + bias + exact GELU --------
__global__ void dwconv_gelu_kernel(const __half* __restrict__ x, const float* __restrict__ w,
                                   const float* __restrict__ bias, __half* __restrict__ y) {
    const int c  = threadIdx.x;
    const float bb = bias[c];
    float wr[9];
    #pragma unroll
    for (int i = 0; i < 9; ++i) wr[i] = w[c * 9 + i];
    #pragma unroll
    for (int sub = 0; sub < 4; ++sub) {
        const int pg = blockIdx.x * 4 + sub;
        const int b    = pg / LQ;
        const int rem  = pg % LQ;
        const int chunk = rem / (HH * WW);
        const int pix   = rem % (HH * WW);
        const int py = pix >> 5, px = pix & 31;
        const __half* xb = x + ((size_t)b * LQ + (size_t)chunk * HH * WW) * HID;
        float acc = bb;
        #pragma unroll
        for (int dy = -1; dy <= 1; dy++) {
            int yy = py + dy;
            if (yy < 0 || yy >= HH) continue;
            #pragma unroll
            for (int dx = -1; dx <= 1; dx++) {
                int xx = px + dx;
                if (xx < 0 || xx >= WW) continue;
                acc += __half2float(xb[(size_t)(yy * WW + xx) * HID + c])
                       * wr[(dy + 1) * 3 + (dx + 1)];
            }
        }
        float gl = 0.5f * acc * (1.f + erff(acc * 0.70710678118654752f));
        y[(size_t)pg * HID + c] = __float2half_rn(gl);
    }
}

// ---------------------------------------------------------------------------
static inline void launch_gemm(const __half* A, const __half* WT, const float* bias,
                               const float* R, const __half* Rh,
                               float* C, __half* Ch, int M, int N, int K) {
    dim3 grid((N + 127) / 128, M / 128);
    gemm_fp16_kernel<<<grid, 256, GEMM_SMEM>>>(A, WT, bias, R, Rh, C, Ch, M, N, K);
}

extern "C" void kernel_launch(void* const* d_in, const int* in_sizes, int n_in,
                              void* d_out, int out_size) {
    const float* query = (const float*)d_in[0];
    const float* refp  = (const float*)d_in[1];
    const float* feat  = (const float*)d_in[2];
    const float* qn_w = (const float*)d_in[7];
    const float* qn_b = (const float*)d_in[8];
    const float* fn_w = (const float*)d_in[9];
    const float* fn_b = (const float*)d_in[10];
    const float* so_w = (const float*)d_in[11];
    const float* so_b = (const float*)d_in[12];
    const float* aw_w = (const float*)d_in[13];
    const float* aw_b = (const float*)d_in[14];
    const float* vp_w = (const float*)d_in[15];
    const float* vp_b = (const float*)d_in[16];
    const float* op_w = (const float*)d_in[17];
    const float* op_b = (const float*)d_in[18];
    const float* ffn_w = (const float*)d_in[19];
    const float* ffn_b = (const float*)d_in[20];
    const float* fc1_w = (const float*)d_in[21];
    const float* fc1_b = (const float*)d_in[22];
    const float* dw_w  = (const float*)d_in[23];
    const float* dw_b  = (const float*)d_in[24];
    const float* fc2_w = (const float*)d_in[25];
    const float* fc2_b = (const float*)d_in[26];
    float* out = (float*)d_out;

    __half *p_qln16, *p_fln16, *p_val16, *p_attn16, *p_x1h, *p_x2h, *p_q2h;
    __half *p_vpT, *p_opT, *p_fc1T, *p_fc2T, *p_w72T;
    float *p_oa, *p_b72;
    cudaGetSymbolAddress((void**)&p_qln16,  g_qln16);
    cudaGetSymbolAddress((void**)&p_fln16,  g_fln16);
    cudaGetSymbolAddress((void**)&p_val16,  g_val16);
    cudaGetSymbolAddress((void**)&p_attn16, g_attn16);
    cudaGetSymbolAddress((void**)&p_x1h,    g_x1h);
    cudaGetSymbolAddress((void**)&p_x2h,    g_x2h);
    cudaGetSymbolAddress((void**)&p_q2h,    g_q2h);
    cudaGetSymbolAddress((void**)&p_vpT,    g_vpT16);
    cudaGetSymbolAddress((void**)&p_opT,    g_opT16);
    cudaGetSymbolAddress((void**)&p_fc1T,   g_fc1T16);
    cudaGetSymbolAddress((void**)&p_fc2T,   g_fc2T16);
    cudaGetSymbolAddress((void**)&p_w72T,   g_w72T16);
    cudaGetSymbolAddress((void**)&p_oa,     g_oa);
    cudaGetSymbolAddress((void**)&p_b72,    g_b72);

    cudaFuncSetAttribute(gemm_fp16_kernel, cudaFuncAttributeMaxDynamicSharedMemorySize, GEMM_SMEM);
    cudaFuncSetAttribute(gemm2_fp16_kernel, cudaFuncAttributeMaxDynamicSharedMemorySize, GEMM_SMEM);

    // 0. fused weight prep (4 transposes + pack) in ONE launch
    prep_kernel<<<PREP_E, 256>>>(vp_w, p_vpT, op_w, p_opT, fc1_w, p_fc1T,
                                 fc2_w, p_fc2T, so_w, so_b, aw_w, aw_b, p_w72T, p_b72);

    // 1. both LayerNorms in ONE launch (fp32 in -> fp16 out)
    ln2_kernel<<<MQ + MF, 192>>>(query, qn_w, qn_b, p_qln16,
                                 feat,  fn_w, fn_b, p_fln16);

    // 2+3. MERGED: oa projection (192 blocks) + value GEMM (1536 blocks)
    {
        const int gx0 = 1,  nb0 = MQ / 128;              // oa:    1 x 192
        const int gx1 = CC / 128;                        // value: 6 x 256
        const int nb1 = gx1 * (MF / 128);                // 1536
        gemm2_fp16_kernel<<<nb0 + nb1, 256, GEMM_SMEM>>>(
            p_qln16, p_w72T, p_b72, p_oa, nullptr, MQ, NOA, CC, nb0, gx0,
            p_fln16, p_vpT,  vp_b,  nullptr, p_val16, MF, CC,  CC, gx1);
    }

    // 4. softmax + bilinear sample + head-reduce (branchless uint4 gathers)
    sample_kernel<<<MQ / 2, 192>>>(refp, p_attn16);

    // 5. output projection + residual(query fp32) -> q2 HALF  (24576 x 768 x 768)
    launch_gemm(p_attn16, p_opT, op_b, query, nullptr, nullptr, p_q2h, MQ, CC, CC);

    // 6. ConvFFN (LN over half q2, fc1 -> half, dwconv, fc2 + half residual -> out)
    ln_h_kernel<<<MQ, 192>>>(p_q2h, ffn_w, ffn_b, p_qln16);
    launch_gemm(p_qln16, p_fc1T, fc1_b, nullptr, nullptr, nullptr, p_x1h, MQ, HID, CC);
    dwconv_gelu_kernel<<<MQ / 4, HID>>>(p_x1h, dw_w, dw_b, p_x2h);
    launch_gemm(p_x2h, p_fc2T, fc2_b, nullptr, p_q2h, out, nullptr, MQ, CC, HID);
}

// round 17
// speedup vs baseline: 1.0287x; 1.0064x over previous
#include <cuda_runtime.h>
#include <cuda_fp16.h>
#include <math.h>
#include <stdint.h>

// ---------------- problem constants (fixed by setup_inputs) ----------------
#define BB   8
#define LQ   3072
#define CC   768
#define LIN  4096          // 64*64 feature tokens
#define HL   64
#define WL   64
#define NH   6
#define NP   4
#define HID  192
#define HH   32
#define WW   32
#define MQ   (BB*LQ)       // 24576
#define MF   (BB*LIN)      // 32768
#define NOA  72            // 48 offs + 24 attn logits, fused

// ---------------- scratch (device globals; no allocs allowed) --------------
__device__ __half g_qln16 [MQ*CC];
__device__ __half g_fln16 [MF*CC];
__device__ __half g_val16 [MF*CC];
__device__ __half g_attn16[MQ*CC];
__device__ __half g_x1h   [MQ*HID];
__device__ __half g_x2h   [MQ*HID];
__device__ __half g_q2h   [MQ*CC];
__device__ float  g_oa    [MQ*NOA];
// transposed fp16 weights [N][K]
__device__ __half g_vpT16 [CC*CC];
__device__ __half g_opT16 [CC*CC];
__device__ __half g_fc1T16[HID*CC];
__device__ __half g_fc2T16[CC*HID];
__device__ __half g_w72T16[NOA*CC];
__device__ float  g_b72   [NOA];

// ---------------- mma / ldmatrix / cp.async helpers -------------------------
__device__ __forceinline__ void mma_fp16(float* d, const uint32_t* a, const uint32_t* b) {
    asm volatile(
        "mma.sync.aligned.m16n8k16.row.col.f32.f16.f16.f32 "
        "{%0,%1,%2,%3}, {%4,%5,%6,%7}, {%8,%9}, {%0,%1,%2,%3};\n"
        : "+f"(d[0]), "+f"(d[1]), "+f"(d[2]), "+f"(d[3])
        : "r"(a[0]), "r"(a[1]), "r"(a[2]), "r"(a[3]), "r"(b[0]), "r"(b[1]));
}
__device__ __forceinline__ void ldsm_x4(uint32_t* r, uint32_t addr) {
    asm volatile("ldmatrix.sync.aligned.m8n8.x4.shared.b16 {%0,%1,%2,%3}, [%4];"
                 : "=r"(r[0]), "=r"(r[1]), "=r"(r[2]), "=r"(r[3]) : "r"(addr));
}
__device__ __forceinline__ void cp16(uint32_t dst, const void* src, bool valid) {
    int sz = valid ? 16 : 0;
    asm volatile("cp.async.cg.shared.global [%0], [%1], 16, %2;\n"
                 :: "r"(dst), "l"(src), "r"(sz));
}
__device__ __forceinline__ void cp_commit() { asm volatile("cp.async.commit_group;\n"); }
template <int N> __device__ __forceinline__ void cp_wait() {
    asm volatile("cp.async.wait_group %0;\n" :: "n"(N));
}

// ---------------- fp16 tensor-core GEMM body --------------------------------
#define ST 36                 // row stride in u32 (32 data + 4 pad) -> conflict-free
#define STB (ST*4)            // 144 bytes
#define TSZ (128 * ST)        // one tile (A or B) in u32 = 4608
#define SSZ (2 * TSZ)         // stage = A + B = 9216 u32
#define NSTAGE 3
#define GEMM_SMEM (NSTAGE * SSZ * 4)   // 110,592 B

__device__ __forceinline__ void gemm_body(
        const __half* __restrict__ A, const __half* __restrict__ WT,
        const float* __restrict__ bias, const float* __restrict__ R,
        const __half* __restrict__ Rh,
        float* __restrict__ C, __half* __restrict__ Ch,
        int M, int N, int K, int bx, int by) {
    extern __shared__ uint32_t sm[];

    const int t    = threadIdx.x;
    const int lane = t & 31;
    const int g    = lane >> 2;
    const int tg   = lane & 3;
    const int wid  = t >> 5;
    const int wm   = wid & 1;
    const int wn   = wid >> 1;

    const int m0 = by * 128;
    const int n0 = bx * 128;

    const int sr = t >> 3;
    const int sc = (t & 7) * 8;
    const uint32_t smem_u = (uint32_t)__cvta_generic_to_shared(sm);
    const uint32_t soff = (uint32_t)(sr * STB + (t & 7) * 16);

    const __half* Abase = A + (size_t)(m0 + sr) * K + sc;
    const __half* WTbase = WT + (size_t)sr * K + sc;

    const int KT = K >> 6;

    auto issue = [&](int ck, int s) {
        const uint32_t sb = smem_u + (uint32_t)(s * SSZ * 4);
        const __half* Ap = Abase + ck * 64;
        const __half* Bp = WTbase + ck * 64;
        #pragma unroll
        for (int j = 0; j < 4; ++j) {
            cp16(sb + soff + (uint32_t)(32 * j * STB),
                 Ap + (size_t)(32 * j) * K, true);
            const int nr = n0 + sr + 32 * j;
            cp16(sb + (uint32_t)(TSZ * 4) + soff + (uint32_t)(32 * j * STB),
                 Bp + (size_t)(n0 + 32 * j) * K, nr < N);
        }
    };

    const int rowA  = (lane & 7) + ((lane >> 3) & 1) * 8;
    const uint32_t kselA = (uint32_t)(lane >> 4) * 16;
    uint32_t aoff[4];
    #pragma unroll
    for (int mt = 0; mt < 4; ++mt)
        aoff[mt] = (uint32_t)((wm * 64 + mt * 16 + rowA) * STB) + kselA;
    const int rowB  = (lane & 7) + ((lane >> 4) & 1) * 8;
    const uint32_t kselB = (uint32_t)((lane >> 3) & 1) * 16;
    uint32_t boff[2];
    #pragma unroll
    for (int p = 0; p < 2; ++p)
        boff[p] = (uint32_t)((wn * 32 + p * 16 + rowB) * STB) + kselB;

    issue(0, 0); cp_commit();
    issue(1, 1); cp_commit();

    float acc[4][4][4] = {};

    for (int it = 0; it < KT; ++it) {
        cp_wait<1>();
        __syncthreads();

        const int nk = it + 2;
        if (nk < KT) issue(nk, nk % NSTAGE);
        cp_commit();

        const int cur = it % NSTAGE;
        const uint32_t abase = smem_u + (uint32_t)(cur * SSZ * 4);
        const uint32_t bbase = abase + (uint32_t)(TSZ * 4);

        #pragma unroll
        for (int ks = 0; ks < 4; ++ks) {
            const uint32_t kbyte = (uint32_t)(ks * 32);
            uint32_t af[4][4], bf[2][4];
            #pragma unroll
            for (int mt = 0; mt < 4; ++mt)
                ldsm_x4(af[mt], abase + aoff[mt] + kbyte);
            #pragma unroll
            for (int p = 0; p < 2; ++p)
                ldsm_x4(bf[p], bbase + boff[p] + kbyte);
            #pragma unroll
            for (int mt = 0; mt < 4; ++mt) {
                mma_fp16(acc[mt][0], af[mt], &bf[0][0]);
                mma_fp16(acc[mt][1], af[mt], &bf[0][2]);
                mma_fp16(acc[mt][2], af[mt], &bf[1][0]);
                mma_fp16(acc[mt][3], af[mt], &bf[1][2]);
            }
        }
    }

    #pragma unroll
    for (int mt = 0; mt < 4; ++mt) {
        const int gm = m0 + wm * 64 + mt * 16 + g;
        #pragma unroll
        for (int nt = 0; nt < 4; ++nt) {
            const int gn = n0 + wn * 32 + nt * 8 + 2 * tg;
            if (gn < N) {
                const float b0 = bias[gn], b1 = bias[gn + 1];
                float2 v0 = make_float2(acc[mt][nt][0] + b0, acc[mt][nt][1] + b1);
                float2 v1 = make_float2(acc[mt][nt][2] + b0, acc[mt][nt][3] + b1);
                const size_t i0 = (size_t)gm * N + gn;
                const size_t i1 = (size_t)(gm + 8) * N + gn;
                if (R) {
                    v0.x += R[i0];     v0.y += R[i0 + 1];
                    v1.x += R[i1];     v1.y += R[i1 + 1];
                }
                if (Rh) {
                    const float2 r0 = __half22float2(*(const __half2*)&Rh[i0]);
                    const float2 r1 = __half22float2(*(const __half2*)&Rh[i1]);
                    v0.x += r0.x; v0.y += r0.y;
                    v1.x += r1.x; v1.y += r1.y;
                }
                if (C) {
                    *(float2*)&C[i0] = v0;
                    *(float2*)&C[i1] = v1;
                }
                if (Ch) {
                    *(__half2*)&Ch[i0] = __floats2half2_rn(v0.x, v0.y);
                    *(__half2*)&Ch[i1] = __floats2half2_rn(v1.x, v1.y);
                }
            }
        }
    }
}

// standalone GEMM launch
__global__ __launch_bounds__(256, 2)
void gemm_fp16_kernel(const __half* __restrict__ A, const __half* __restrict__ WT,
                      const float* __restrict__ bias, const float* __restrict__ R,
                      const __half* __restrict__ Rh,
                      float* __restrict__ C, __half* __restrict__ Ch,
                      int M, int N, int K) {
    gemm_body(A, WT, bias, R, Rh, C, Ch, M, N, K, blockIdx.x, blockIdx.y);
}

// merged dual GEMM: blocks [0, nb0) -> GEMM0, rest -> GEMM1 (1D grid)
__global__ __launch_bounds__(256, 2)
void gemm2_fp16_kernel(const __half* A0, const __half* W0, const float* b0,
                       float* C0, __half* Ch0, int M0, int N0, int K0, int nb0, int gx0,
                       const __half* A1, const __half* W1, const float* b1,
                       float* C1, __half* Ch1, int M1, int N1, int K1, int gx1) {
    int bid = blockIdx.x;
    if (bid < nb0) {
        gemm_body(A0, W0, b0, nullptr, nullptr, C0, Ch0, M0, N0, K0,
                  bid % gx0, bid / gx0);
    } else {
        bid -= nb0;
        gemm_body(A1, W1, b1, nullptr, nullptr, C1, Ch1, M1, N1, K1,
                  bid % gx1, bid / gx1);
    }
}

// ---------------- LayerNorm bodies ------------------------------------------
__device__ __forceinline__ void ln_finish(float s, float ss, int t,
                                          float& mean, float& inv) {
    __shared__ float red0[6], red1[6];
    #pragma unroll
    for (int o = 16; o; o >>= 1) {
        s  += __shfl_down_sync(0xffffffffu, s,  o);
        ss += __shfl_down_sync(0xffffffffu, ss, o);
    }
    if ((t & 31) == 0) { red0[t >> 5] = s; red1[t >> 5] = ss; }
    __syncthreads();
    float st = 0.f, sst = 0.f;
    #pragma unroll
    for (int i = 0; i < 6; ++i) { st += red0[i]; sst += red1[i]; }
    mean = st * (1.f / CC);
    const float var = sst * (1.f / CC) - mean * mean;
    inv = rsqrtf(var + 1e-6f);
}

__device__ __forceinline__ void ln_row(const float* __restrict__ xr,
                                       const float* __restrict__ w,
                                       const float* __restrict__ b,
                                       __half* __restrict__ yr, int t) {
    const float4 v = ((const float4*)xr)[t];
    float mean, inv;
    ln_finish(v.x + v.y + v.z + v.w,
              v.x*v.x + v.y*v.y + v.z*v.z + v.w*v.w, t, mean, inv);
    const float4 wv = ((const float4*)w)[t];
    const float4 bv = ((const float4*)b)[t];
    __half2 h0 = __floats2half2_rn((v.x - mean) * inv * wv.x + bv.x,
                                   (v.y - mean) * inv * wv.y + bv.y);
    __half2 h1 = __floats2half2_rn((v.z - mean) * inv * wv.z + bv.z,
                                   (v.w - mean) * inv * wv.w + bv.w);
    uint2 o2 = make_uint2(*(uint32_t*)&h0, *(uint32_t*)&h1);
    *(uint2*)&yr[t * 4] = o2;
}

// LN with fp16 input (for ffn LN over q2h)
__global__ void ln_h_kernel(const __half* __restrict__ x, const float* __restrict__ w,
                            const float* __restrict__ b, __half* __restrict__ y) {
    const int row = blockIdx.x;
    const int t = threadIdx.x;
    const uint2 raw = *(const uint2*)&x[(size_t)row * CC + t * 4];
    const float2 f0 = __half22float2(*(const __half2*)&raw.x);
    const float2 f1 = __half22float2(*(const __half2*)&raw.y);
    float mean, inv;
    ln_finish(f0.x + f0.y + f1.x + f1.y,
              f0.x*f0.x + f0.y*f0.y + f1.x*f1.x + f1.y*f1.y, t, mean, inv);
    const float4 wv = ((const float4*)w)[t];
    const float4 bv = ((const float4*)b)[t];
    __half2 h0 = __floats2half2_rn((f0.x - mean) * inv * wv.x + bv.x,
                                   (f0.y - mean) * inv * wv.y + bv.y);
    __half2 h1 = __floats2half2_rn((f1.x - mean) * inv * wv.z + bv.z,
                                   (f1.y - mean) * inv * wv.w + bv.w);
    uint2 o2 = make_uint2(*(uint32_t*)&h0, *(uint32_t*)&h1);
    *(uint2*)&y[(size_t)row * CC + t * 4] = o2;
}

// ---------------- transpose sub-tile with 192 threads (32x6) ---------------
__device__ __forceinline__ void transp_tile192(const float* __restrict__ src,
                                               __half* __restrict__ dst,
                                               int K, int N, int bx, int by, int t) {
    __shared__ float tile[32][33];
    const int kb = by * 32, nb = bx * 32;
    const int tx = t & 31, ty = t >> 5;   // 32 x 6
    #pragma unroll
    for (int i = 0; i < 32; i += 6) {
        const int r = ty + i;
        if (r < 32) {
            const int k = kb + r, n = nb + tx;
            tile[r][tx] = (k < K && n < N) ? src[(size_t)k * N + n] : 0.f;
        }
    }
    __syncthreads();
    #pragma unroll
    for (int i = 0; i < 32; i += 6) {
        const int r = ty + i;
        if (r < 32) {
            const int n = nb + r, k = kb + tx;
            if (n < N && k < K) dst[(size_t)n * K + k] = __float2half_rn(tile[tx][r]);
        }
    }
}

// ---------------- MERGED prep + dual-LN kernel (192 threads) ----------------
// blocks [0,PREP) do weight prep; blocks [PREP, PREP+MQ+MF) do LayerNorm rows.
#define P_A 576                 // vp   24x24
#define P_B 1152                // op   24x24
#define P_C 1296                // fc1  6x24
#define P_D 1440                // fc2  24x6
#define P_PK 1728               // pack: 288 blocks x 192 thr
#define P_END (P_PK + MQ + MF)
__global__ void prepln_kernel(const float* __restrict__ vp_w,  __half* __restrict__ vpT,
                              const float* __restrict__ op_w,  __half* __restrict__ opT,
                              const float* __restrict__ fc1_w, __half* __restrict__ fc1T,
                              const float* __restrict__ fc2_w, __half* __restrict__ fc2T,
                              const float* __restrict__ so_w, const float* __restrict__ so_b,
                              const float* __restrict__ aw_w, const float* __restrict__ aw_b,
                              __half* __restrict__ w72T, float* __restrict__ b72,
                              const float* __restrict__ q, const float* __restrict__ qw,
                              const float* __restrict__ qb, __half* __restrict__ qy,
                              const float* __restrict__ f, const float* __restrict__ fw,
                              const float* __restrict__ fb, __half* __restrict__ fy) {
    const int b = blockIdx.x;
    const int t = threadIdx.x;
    if (b < P_A) {
        transp_tile192(vp_w, vpT, CC, CC, b % 24, b / 24, t);
    } else if (b < P_B) {
        const int c = b - P_A;
        transp_tile192(op_w, opT, CC, CC, c % 24, c / 24, t);
    } else if (b < P_C) {
        const int c = b - P_B;
        transp_tile192(fc1_w, fc1T, CC, HID, c % 6, c / 6, t);
    } else if (b < P_D) {
        const int c = b - P_C;
        transp_tile192(fc2_w, fc2T, HID, CC, c % 24, c / 24, t);
    } else if (b < P_PK) {
        const int i = (b - P_D) * 192 + t;
        if (i < NOA * CC) {
            const int n = i / CC, k = i % CC;
            const float v = (n < 48) ? so_w[k * 48 + n] : aw_w[k * 24 + (n - 48)];
            w72T[i] = __float2half_rn(v);
        }
        if (i < NOA) b72[i] = (i < 48) ? so_b[i] : aw_b[i - 48];
    } else {
        int row = b - P_PK;
        if (row < MQ) {
            ln_row(q + (size_t)row * CC, qw, qb, qy + (size_t)row * CC, t);
        } else {
            row -= MQ;
            ln_row(f + (size_t)row * CC, fw, fb, fy + (size_t)row * CC, t);
        }
    }
}

// ------- softmax(attn weights) + bilinear sample + weighted reduce ---------
// One block per 2 queries; 192 threads = 2 x 96, each thread owns 8 channels.
// == Round-14 proven formulation (conditional gathers, fp32 accumulate) ==
__global__ void sample_kernel(const float* __restrict__ refp, __half* __restrict__ attn) {
    const int q0 = blockIdx.x * 2;
    __shared__ float cw[2][NH * NP][4];
    __shared__ int   ci[2][NH * NP][4];
    __shared__ float lg[2][NH * NP];
    const int t = threadIdx.x;
    if (t < 2 * NH * NP) {
        const int qi = t / (NH * NP), j = t % (NH * NP);
        lg[qi][j] = g_oa[(size_t)(q0 + qi) * NOA + 48 + j];
    }
    __syncthreads();
    if (t < 2 * NH * NP) {
        const int qi = t / (NH * NP), j = t % (NH * NP);
        const int q = q0 + qi;
        const int h = j >> 2;
        float l0 = lg[qi][h*4+0], l1 = lg[qi][h*4+1], l2 = lg[qi][h*4+2], l3 = lg[qi][h*4+3];
        float m  = fmaxf(fmaxf(l0, l1), fmaxf(l2, l3));
        float e0 = __expf(l0-m), e1 = __expf(l1-m), e2 = __expf(l2-m), e3 = __expf(l3-m);
        float aw = __expf(lg[qi][j]-m) / (e0 + e1 + e2 + e3);
        float rx = refp[(size_t)q * 2 + 0];
        float ry = refp[(size_t)q * 2 + 1];
        float ox = g_oa[(size_t)q * NOA + j*2 + 0];
        float oy = g_oa[(size_t)q * NOA + j*2 + 1];
        float x = (rx + ox * (1.f / WL)) * WL - 0.5f;
        float y = (ry + oy * (1.f / HL)) * HL - 0.5f;
        float x0f = floorf(x), y0f = floorf(y);
        float wx = x - x0f, wy = y - y0f;
        int x0 = (int)x0f, y0 = (int)y0f;
        float ws[4] = {(1.f-wy)*(1.f-wx), (1.f-wy)*wx, wy*(1.f-wx), wy*wx};
        const int dys[4] = {0,0,1,1}, dxs[4] = {0,1,0,1};
        #pragma unroll
        for (int c2 = 0; c2 < 4; c2++) {
            int xi = x0 + dxs[c2], yi = y0 + dys[c2];
            bool valid = (xi >= 0) && (xi < WL) && (yi >= 0) && (yi < HL);
            ci[qi][j][c2] = valid ? (yi * WL + xi) : -1;
            cw[qi][j][c2] = valid ? ws[c2] * aw : 0.f;
        }
    }
    __syncthreads();
    const int qi = t / 96;           // query within pair
    const int tc = t % 96;           // channel group: halves tc*8 .. tc*8+7
    const int h  = tc >> 4;          // head = (tc*8)/128
    const int q  = q0 + qi;
    const __half* vb = g_val16 + (size_t)(q / LQ) * LIN * CC + tc * 8;
    float a0 = 0.f, a1 = 0.f, a2 = 0.f, a3 = 0.f;
    float a4 = 0.f, a5 = 0.f, a6 = 0.f, a7 = 0.f;
    #pragma unroll
    for (int j = 0; j < NP; ++j)
        #pragma unroll
        for (int c2 = 0; c2 < 4; ++c2) {
            const int idx = ci[qi][h * NP + j][c2];
            if (idx >= 0) {
                const float wgt = cw[qi][h * NP + j][c2];
                const uint4 raw = *(const uint4*)&vb[(size_t)idx * CC];
                const float2 f0 = __half22float2(*(const __half2*)&raw.x);
                const float2 f1 = __half22float2(*(const __half2*)&raw.y);
                const float2 f2 = __half22float2(*(const __half2*)&raw.z);
                const float2 f3 = __half22float2(*(const __half2*)&raw.w);
                a0 += f0.x * wgt; a1 += f0.y * wgt;
                a2 += f1.x * wgt; a3 += f1.y * wgt;
                a4 += f2.x * wgt; a5 += f2.y * wgt;
                a6 += f3.x * wgt; a7 += f3.y * wgt;
            }
        }
    __half2 h0 = __floats2half2_rn(a0, a1);
    __half2 h1 = __floats2half2_rn(a2, a3);
    __half2 h2 = __floats2half2_rn(a4, a5);
    __half2 h3 = __floats2half2_rn(a6, a7);
    uint4 o4 = make_uint4(*(uint32_t*)&h0, *(uint32_t*)&h1,
                          *(uint32_t*)&h2, *(uint32_t*)&h3);
    *(uint4*)&attn[(size_t)q * CC + tc * 8] = o4;
}

// ---------- depthwise 3x3 conv (SAME, zero pad) + bias + exact GELU --------
__global__ void dwconv_gelu_kernel(const __half* __restrict__ x, const float* __restrict__ w,
                                   const float* __restrict__ bias, __half* __restrict__ y) {
    const int c  = threadIdx.x;
    const float bb = bias[c];
    float wr[9];
    #pragma unroll
    for (int i = 0; i < 9; ++i) wr[i] = w[c * 9 + i];
    #pragma unroll
    for (int sub = 0; sub < 4; ++sub) {
        const int pg = blockIdx.x * 4 + sub;
        const int b    = pg / LQ;
        const int rem  = pg % LQ;
        const int chunk = rem / (HH * WW);
        const int pix   = rem % (HH * WW);
        const int py = pix >> 5, px = pix & 31;
        const __half* xb = x + ((size_t)b * LQ + (size_t)chunk * HH * WW) * HID;
        float acc = bb;
        #pragma unroll
        for (int dy = -1; dy <= 1; dy++) {
            int yy = py + dy;
            if (yy < 0 || yy >= HH) continue;
            #pragma unroll
            for (int dx = -1; dx <= 1; dx++) {
                int xx = px + dx;
                if (xx < 0 || xx >= WW) continue;
                acc += __half2float(xb[(size_t)(yy * WW + xx) * HID + c])
                       * wr[(dy + 1) * 3 + (dx + 1)];
            }
        }
        float gl = 0.5f * acc * (1.f + erff(acc * 0.70710678118654752f));
        y[(size_t)pg * HID + c] = __float2half_rn(gl);
    }
}

// ---------------------------------------------------------------------------
static inline void launch_gemm(const __half* A, const __half* WT, const float* bias,
                               const float* R, const __half* Rh,
                               float* C, __half* Ch, int M, int N, int K) {
    dim3 grid((N + 127) / 128, M / 128);
    gemm_fp16_kernel<<<grid, 256, GEMM_SMEM>>>(A, WT, bias, R, Rh, C, Ch, M, N, K);
}

extern "C" void kernel_launch(void* const* d_in, const int* in_sizes, int n_in,
                              void* d_out, int out_size) {
    const float* query = (const float*)d_in[0];
    const float* refp  = (const float*)d_in[1];
    const float* feat  = (const float*)d_in[2];
    const float* qn_w = (const float*)d_in[7];
    const float* qn_b = (const float*)d_in[8];
    const float* fn_w = (const float*)d_in[9];
    const float* fn_b = (const float*)d_in[10];
    const float* so_w = (const float*)d_in[11];
    const float* so_b = (const float*)d_in[12];
    const float* aw_w = (const float*)d_in[13];
    const float* aw_b = (const float*)d_in[14];
    const float* vp_w = (const float*)d_in[15];
    const float* vp_b = (const float*)d_in[16];
    const float* op_w = (const float*)d_in[17];
    const float* op_b = (const float*)d_in[18];
    const float* ffn_w = (const float*)d_in[19];
    const float* ffn_b = (const float*)d_in[20];
    const float* fc1_w = (const float*)d_in[21];
    const float* fc1_b = (const float*)d_in[22];
    const float* dw_w  = (const float*)d_in[23];
    const float* dw_b  = (const float*)d_in[24];
    const float* fc2_w = (const float*)d_in[25];
    const float* fc2_b = (const float*)d_in[26];
    float* out = (float*)d_out;

    __half *p_qln16, *p_fln16, *p_val16, *p_attn16, *p_x1h, *p_x2h, *p_q2h;
    __half *p_vpT, *p_opT, *p_fc1T, *p_fc2T, *p_w72T;
    float *p_oa, *p_b72;
    cudaGetSymbolAddress((void**)&p_qln16,  g_qln16);
    cudaGetSymbolAddress((void**)&p_fln16,  g_fln16);
    cudaGetSymbolAddress((void**)&p_val16,  g_val16);
    cudaGetSymbolAddress((void**)&p_attn16, g_attn16);
    cudaGetSymbolAddress((void**)&p_x1h,    g_x1h);
    cudaGetSymbolAddress((void**)&p_x2h,    g_x2h);
    cudaGetSymbolAddress((void**)&p_q2h,    g_q2h);
    cudaGetSymbolAddress((void**)&p_vpT,    g_vpT16);
    cudaGetSymbolAddress((void**)&p_opT,    g_opT16);
    cudaGetSymbolAddress((void**)&p_fc1T,   g_fc1T16);
    cudaGetSymbolAddress((void**)&p_fc2T,   g_fc2T16);
    cudaGetSymbolAddress((void**)&p_w72T,   g_w72T16);
    cudaGetSymbolAddress((void**)&p_oa,     g_oa);
    cudaGetSymbolAddress((void**)&p_b72,    g_b72);

    cudaFuncSetAttribute(gemm_fp16_kernel, cudaFuncAttributeMaxDynamicSharedMemorySize, GEMM_SMEM);
    cudaFuncSetAttribute(gemm2_fp16_kernel, cudaFuncAttributeMaxDynamicSharedMemorySize, GEMM_SMEM);

    // 0+1. MERGED: weight prep (1728 blocks) + both LayerNorms (57344 blocks)
    prepln_kernel<<<P_END, 192>>>(vp_w, p_vpT, op_w, p_opT, fc1_w, p_fc1T,
                                  fc2_w, p_fc2T, so_w, so_b, aw_w, aw_b,
                                  p_w72T, p_b72,
                                  query, qn_w, qn_b, p_qln16,
                                  feat,  fn_w, fn_b, p_fln16);

    // 2+3. MERGED: oa projection (192 blocks) + value GEMM (1536 blocks)
    {
        const int gx0 = 1,  nb0 = MQ / 128;              // oa:    1 x 192
        const int gx1 = CC / 128;                        // value: 6 x 256
        const int nb1 = gx1 * (MF / 128);                // 1536
        gemm2_fp16_kernel<<<nb0 + nb1, 256, GEMM_SMEM>>>(
            p_qln16, p_w72T, p_b72, p_oa, nullptr, MQ, NOA, CC, nb0, gx0,
            p_fln16, p_vpT,  vp_b,  nullptr, p_val16, MF, CC,  CC, gx1);
    }

    // 4. softmax + bilinear sample + head-reduce (R14 formulation)
    sample_kernel<<<MQ / 2, 192>>>(refp, p_attn16);

    // 5. output projection + residual(query fp32) -> q2 HALF  (24576 x 768 x 768)
    launch_gemm(p_attn16, p_opT, op_b, query, nullptr, nullptr, p_q2h, MQ, CC, CC);

    // 6. ConvFFN (LN over half q2, fc1 -> half, dwconv, fc2 + half residual -> out)
    ln_h_kernel<<<MQ, 192>>>(p_q2h, ffn_w, ffn_b, p_qln16);
    launch_gemm(p_qln16, p_fc1T, fc1_b, nullptr, nullptr, nullptr, p_x1h, MQ, HID, CC);
    dwconv_gelu_kernel<<<MQ / 4, HID>>>(p_x1h, dw_w, dw_b, p_x2h);
    launch_gemm(p_x2h, p_fc2T, fc2_b, nullptr, p_q2h, out, nullptr, MQ, CC, HID);
}